// round 2
// baseline (speedup 1.0000x reference)
#include <cuda_runtime.h>
#include <cstdint>

// ----------------------------------------------------------------------------
// Problem constants
// ----------------------------------------------------------------------------
#define BS_      1024
#define KTOT     33154
#define HID      512
#define ODIM     129
#define ST_LEN   16641
#define AT_LEN_  129
#define ST1_LEN  16384
#define B_AT     16641      /* st | at boundary   */
#define B_ST1    16770      /* at | st1 boundary  */

#define MT       256        /* CTA tile M (batch)  */
#define NT       128        /* CTA tile N (hidden) */
#define CHUNK    32         /* K per stage         */
#define NCHUNK   1037       /* ceil(33154/32)      */
#define SPLIT    8
#define CPS      130        /* chunks per split    */

#define A_BYTES  (MT * CHUNK * 4)          /* 32768 */
#define B_BYTES  (NT * CHUNK * 4)          /* 16384 */
#define STAGE    (A_BYTES + B_BYTES)       /* 49152 */
#define SMEM_TOTAL (1024 + 2 * STAGE)      /* 99328 */

// split-K partials: 8 * 1024 * 512 * 4 = 16 MB
__device__ float g_partial[SPLIT * BS_ * HID];

// ----------------------------------------------------------------------------
// Helpers (sm_103-plain-safe PTX only: ldmatrix / mma.sync / cvt.rna.tf32)
// ----------------------------------------------------------------------------
__device__ __forceinline__ uint32_t smem_u32(const void* p) {
    uint32_t a;
    asm("{ .reg .u64 t; cvta.to.shared.u64 t, %1; cvt.u32.u64 %0, t; }" : "=r"(a) : "l"(p));
    return a;
}

__device__ __forceinline__ uint32_t swz(uint32_t off) {
    return off ^ ((off >> 3) & 0x70u);
}

__device__ __forceinline__ uint32_t f32_to_tf32(float x) {
    uint32_t r;
    asm("cvt.rna.tf32.f32 %0, %1;" : "=r"(r) : "f"(x));
    return r;
}

__device__ __forceinline__ void ldsm_x4(uint32_t r[4], uint32_t addr) {
    asm volatile("ldmatrix.sync.aligned.m8n8.x4.shared.b16 {%0,%1,%2,%3}, [%4];"
                 : "=r"(r[0]), "=r"(r[1]), "=r"(r[2]), "=r"(r[3]) : "r"(addr));
}

__device__ __forceinline__ void ldsm_x2(uint32_t r[2], uint32_t addr) {
    asm volatile("ldmatrix.sync.aligned.m8n8.x2.shared.b16 {%0,%1}, [%2];"
                 : "=r"(r[0]), "=r"(r[1]) : "r"(addr));
}

__device__ __forceinline__ void mma_tf32(float c[4], const uint32_t a[4], const uint32_t b[2]) {
    asm volatile(
        "mma.sync.aligned.m16n8k8.row.col.f32.tf32.tf32.f32 "
        "{%0,%1,%2,%3}, {%4,%5,%6,%7}, {%8,%9}, {%0,%1,%2,%3};"
        : "+f"(c[0]), "+f"(c[1]), "+f"(c[2]), "+f"(c[3])
        : "r"(a[0]), "r"(a[1]), "r"(a[2]), "r"(a[3]), "r"(b[0]), "r"(b[1]));
}

__device__ __forceinline__ void sts32(uint32_t addr, uint32_t v) {
    asm volatile("st.shared.b32 [%0], %1;" :: "r"(addr), "r"(v));
}
__device__ __forceinline__ void sts128(uint32_t addr, uint32_t v0, uint32_t v1, uint32_t v2, uint32_t v3) {
    asm volatile("st.shared.v4.b32 [%0], {%1,%2,%3,%4};" :: "r"(addr), "r"(v0), "r"(v1), "r"(v2), "r"(v3));
}

// ----------------------------------------------------------------------------
// GEMM1: H_partial = X @ W1, tf32 mma.sync, split-K.
// grid = 128 CTAs = 4 ntile x 4 mtile x 8 split, 256 threads.
// SMEM layout per stage: A [256 m][32 k] (128B rows, SW128 swz),
//                        B [128 n][32 k] (128B rows, SW128 swz).
// ----------------------------------------------------------------------------
__global__ void __launch_bounds__(256, 1) gemm1_kernel(
    const float* __restrict__ st, const float* __restrict__ at,
    const float* __restrict__ st1, const float* __restrict__ W1)
{
    extern __shared__ char smem_raw[];
    uint32_t base = smem_u32(smem_raw);
    base = (base + 1023u) & ~1023u;

    const int tid = threadIdx.x;
    const int l   = tid & 31;
    const int w   = tid >> 5;
    const int wm  = w >> 1;       // 0..3
    const int wn  = w & 1;        // 0..1

    const int bx = blockIdx.x;
    const int nt = bx & 3;
    const int mt = (bx >> 2) & 3;
    const int sp = bx >> 4;

    const int c0  = sp * CPS;
    int nch = NCHUNK - c0;
    if (nch > CPS) nch = CPS;

    const int mbase = mt * MT + w * 32;
    const int bg = w & 3;                 // B n-group (32 n each)
    const int bh = w >> 2;                // B k-half  (16 k each)
    const int bn = nt * NT + bg * 32 + l; // global n for B fill

    // ---- chunk load (GMEM -> regs, with rna tf32 rounding) ----
    auto load_chunk = [&](int chunk, uint32_t aPre[32], uint32_t bPre[16]) {
        const int k0 = chunk * CHUNK;
        // A: this lane's k column, 32 m rows
        const int kk = k0 + l;
        const float* src = 0; int stride = 0;
        if (kk < B_AT)          { src = st  + kk;            stride = ST_LEN;  }
        else if (kk < B_ST1)    { src = at  + (kk - B_AT);   stride = AT_LEN_; }
        else if (kk < KTOT)     { src = st1 + (kk - B_ST1);  stride = ST1_LEN; }
#pragma unroll
        for (int r = 0; r < 32; ++r) {
            float v = src ? __ldg(src + (size_t)(mbase + r) * stride) : 0.0f;
            aPre[r] = f32_to_tf32(v);
        }
        // B: this lane's n column, 16 k rows (transpose W1[k][n] -> [n][k])
#pragma unroll
        for (int j = 0; j < 16; ++j) {
            const int k = k0 + bh * 16 + j;
            float v = (k < KTOT) ? __ldg(W1 + (size_t)k * HID + bn) : 0.0f;
            bPre[j] = f32_to_tf32(v);
        }
    };

    // ---- chunk store (regs -> SMEM, swizzled) ----
    auto store_chunk = [&](int s, const uint32_t aPre[32], const uint32_t bPre[16]) {
        const uint32_t Ab = base + (uint32_t)s * STAGE;
        const uint32_t Bb = Ab + A_BYTES;
#pragma unroll
        for (int r = 0; r < 32; ++r)
            sts32(Ab + swz((uint32_t)((w * 32 + r) * 128 + l * 4)), aPre[r]);
#pragma unroll
        for (int j4 = 0; j4 < 4; ++j4) {
            const uint32_t off = swz((uint32_t)((bg * 32 + l) * 128 + (bh * 16 + j4 * 4) * 4));
            sts128(Bb + off, bPre[j4 * 4], bPre[j4 * 4 + 1], bPre[j4 * 4 + 2], bPre[j4 * 4 + 3]);
        }
    };

    // ---- fragment smem offsets (pre-swizzle, in-tile) ----
    uint32_t relA[4], relB[8];
#pragma unroll
    for (int t = 0; t < 4; ++t)
        relA[t] = (uint32_t)((wm * 64 + t * 16 + (l & 7) + ((l >> 3) & 1) * 8) * 128
                             + ((l >> 4) & 1) * 16);
    const int lm = l & 15;
#pragma unroll
    for (int u = 0; u < 8; ++u)
        relB[u] = (uint32_t)((wn * 64 + u * 8 + (lm & 7)) * 128 + ((lm >> 3) & 1) * 16);

    float acc[4][8][4];
#pragma unroll
    for (int t = 0; t < 4; ++t)
#pragma unroll
        for (int u = 0; u < 8; ++u)
#pragma unroll
            for (int j = 0; j < 4; ++j) acc[t][u][j] = 0.0f;

    // ---- prologue ----
    {
        uint32_t aPre[32], bPre[16];
        load_chunk(c0, aPre, bPre);
        store_chunk(0, aPre, bPre);
    }
    __syncthreads();

    // ---- main loop ----
    for (int i = 0; i < nch; ++i) {
        const int s = i & 1;
        const uint32_t Ab = base + (uint32_t)s * STAGE;
        const uint32_t Bb = Ab + A_BYTES;

        uint32_t aPre[32], bPre[16];
        const bool pf = (i + 1 < nch);
        if (pf) load_chunk(c0 + i + 1, aPre, bPre);

#pragma unroll
        for (int ks = 0; ks < 4; ++ks) {
            uint32_t afr[4][4], bfr[8][2];
#pragma unroll
            for (int t = 0; t < 4; ++t) ldsm_x4(afr[t], Ab + swz(relA[t] + ks * 32));
#pragma unroll
            for (int u = 0; u < 8; ++u) ldsm_x2(bfr[u], Bb + swz(relB[u] + ks * 32));
#pragma unroll
            for (int t = 0; t < 4; ++t)
#pragma unroll
                for (int u = 0; u < 8; ++u)
                    mma_tf32(acc[t][u], afr[t], bfr[u]);
        }

        if (pf) store_chunk(s ^ 1, aPre, bPre);
        __syncthreads();
    }

    // ---- epilogue: write split-K partials ----
    float* outp = g_partial + (size_t)sp * BS_ * HID;
#pragma unroll
    for (int t = 0; t < 4; ++t) {
        const int row0 = mt * MT + wm * 64 + t * 16 + (l >> 2);
#pragma unroll
        for (int u = 0; u < 8; ++u) {
            const int col = nt * NT + wn * 64 + u * 8 + (l & 3) * 2;
            float2 v0; v0.x = acc[t][u][0]; v0.y = acc[t][u][1];
            float2 v1; v1.x = acc[t][u][2]; v1.y = acc[t][u][3];
            *(float2*)(outp + (size_t)row0 * HID + col)       = v0;
            *(float2*)(outp + (size_t)(row0 + 8) * HID + col) = v1;
        }
    }
}

// ----------------------------------------------------------------------------
// Kernel 2: reduce split-K partials + b1 + ReLU, then H @ W2 + b2.
// ----------------------------------------------------------------------------
__global__ void __launch_bounds__(160) mlp2_kernel(
    const float* __restrict__ b1, const float* __restrict__ W2,
    const float* __restrict__ b2, float* __restrict__ out)
{
    __shared__ float h_s[8 * HID];
    const int tid = threadIdx.x;
    const int row0 = blockIdx.x * 8;

    for (int idx = tid; idx < 8 * HID; idx += 160) {
        const int r = idx >> 9;
        const int c = idx & 511;
        float s = b1[c];
#pragma unroll
        for (int sp = 0; sp < SPLIT; ++sp)
            s += g_partial[((size_t)sp * BS_ + (row0 + r)) * HID + c];
        h_s[idx] = fmaxf(s, 0.0f);
    }
    __syncthreads();

    const int j = tid;
    if (j < ODIM) {
        float acc[8];
#pragma unroll
        for (int r = 0; r < 8; ++r) acc[r] = b2[j];
#pragma unroll 4
        for (int k = 0; k < HID; ++k) {
            const float wv = W2[k * ODIM + j];
#pragma unroll
            for (int r = 0; r < 8; ++r)
                acc[r] = fmaf(h_s[r * HID + k], wv, acc[r]);
        }
#pragma unroll
        for (int r = 0; r < 8; ++r)
            out[(size_t)(row0 + r) * ODIM + j] = acc[r];
    }
}

// ----------------------------------------------------------------------------
// Launch
// ----------------------------------------------------------------------------
extern "C" void kernel_launch(void* const* d_in, const int* in_sizes, int n_in,
                              void* d_out, int out_size) {
    const float* st  = (const float*)d_in[0];
    const float* at  = (const float*)d_in[1];
    const float* st1 = (const float*)d_in[2];
    const float* W1  = (const float*)d_in[3];
    const float* b1  = (const float*)d_in[4];
    const float* W2  = (const float*)d_in[5];
    const float* b2  = (const float*)d_in[6];
    float* out = (float*)d_out;

    cudaFuncSetAttribute(gemm1_kernel, cudaFuncAttributeMaxDynamicSharedMemorySize, SMEM_TOTAL);

    gemm1_kernel<<<128, 256, SMEM_TOTAL>>>(st, at, st1, W1);
    mlp2_kernel<<<BS_ / 8, 160>>>(b1, W2, b2, out);
}

// round 4
// speedup vs baseline: 1.3476x; 1.3476x over previous
#include <cuda_runtime.h>
#include <cstdint>

// ----------------------------------------------------------------------------
// Problem constants
// ----------------------------------------------------------------------------
#define BS_      1024
#define KTOT     33154
#define HID      512
#define ODIM     129
#define ST_LEN   16641
#define AT_LEN_  129
#define ST1_LEN  16384
#define B_AT     16641      /* st | at boundary   */
#define B_ST1    16770      /* at | st1 boundary  */

#define MT       256        /* CTA tile M (batch)  */
#define NT       128        /* CTA tile N (hidden) */
#define CHUNK    32         /* K per stage         */
#define NCHUNK   1037       /* ceil(33154/32)      */
#define SPLIT    9
#define CPS      116        /* ceil(1037/9)        */

#define A_BYTES  (MT * CHUNK * 4)          /* 32768 */
#define B_BYTES  (NT * CHUNK * 4)          /* 16384 */
#define STAGE    (A_BYTES + B_BYTES)       /* 49152 */
#define SMEM_TOTAL (1024 + 2 * STAGE)      /* 99328 */

// split-K partials: 9 * 1024 * 512 * 4 = 18.9 MB
__device__ float g_partial[SPLIT * BS_ * HID];

// ----------------------------------------------------------------------------
// Helpers (plain-sm_103-safe PTX only: ldmatrix / mma.sync / cvt.rna.tf32)
// ----------------------------------------------------------------------------
__device__ __forceinline__ uint32_t smem_u32(const void* p) {
    uint32_t a;
    asm("{ .reg .u64 t; cvta.to.shared.u64 t, %1; cvt.u32.u64 %0, t; }" : "=r"(a) : "l"(p));
    return a;
}

__device__ __forceinline__ uint32_t swz(uint32_t off) {
    return off ^ ((off >> 3) & 0x70u);
}

__device__ __forceinline__ uint32_t f32_to_tf32(float x) {
    uint32_t r;
    asm("cvt.rna.tf32.f32 %0, %1;" : "=r"(r) : "f"(x));
    return r;
}

__device__ __forceinline__ void ldsm_x4(uint32_t r[4], uint32_t addr) {
    asm volatile("ldmatrix.sync.aligned.m8n8.x4.shared.b16 {%0,%1,%2,%3}, [%4];"
                 : "=r"(r[0]), "=r"(r[1]), "=r"(r[2]), "=r"(r[3]) : "r"(addr));
}

__device__ __forceinline__ void ldsm_x2(uint32_t r[2], uint32_t addr) {
    asm volatile("ldmatrix.sync.aligned.m8n8.x2.shared.b16 {%0,%1}, [%2];"
                 : "=r"(r[0]), "=r"(r[1]) : "r"(addr));
}

__device__ __forceinline__ void mma_tf32(float c[4], const uint32_t a[4], const uint32_t b[2]) {
    asm volatile(
        "mma.sync.aligned.m16n8k8.row.col.f32.tf32.tf32.f32 "
        "{%0,%1,%2,%3}, {%4,%5,%6,%7}, {%8,%9}, {%0,%1,%2,%3};"
        : "+f"(c[0]), "+f"(c[1]), "+f"(c[2]), "+f"(c[3])
        : "r"(a[0]), "r"(a[1]), "r"(a[2]), "r"(a[3]), "r"(b[0]), "r"(b[1]));
}

__device__ __forceinline__ void sts32(uint32_t addr, uint32_t v) {
    asm volatile("st.shared.b32 [%0], %1;" :: "r"(addr), "r"(v));
}
__device__ __forceinline__ void sts128(uint32_t addr, uint32_t v0, uint32_t v1, uint32_t v2, uint32_t v3) {
    asm volatile("st.shared.v4.b32 [%0], {%1,%2,%3,%4};" :: "r"(addr), "r"(v0), "r"(v1), "r"(v2), "r"(v3));
}

// ----------------------------------------------------------------------------
// GEMM1: H_partial = X @ W1, tf32 mma.sync, split-K=9.
// grid = 144 CTAs = 4 nt x 4 mt x 9 split, 512 threads (16 warps).
// SMEM per stage: A [256 m][32 k], B [128 n][32 k], 128B rows, SW128 swizzle.
// Warp tile 64(M) x 32(N): wm = w>>2, wn = w&3.
// ----------------------------------------------------------------------------
__global__ void __launch_bounds__(512, 1) gemm1_kernel(
    const float* __restrict__ st, const float* __restrict__ at,
    const float* __restrict__ st1, const float* __restrict__ W1)
{
    extern __shared__ char smem_raw[];
    uint32_t base = smem_u32(smem_raw);
    base = (base + 1023u) & ~1023u;

    const int tid = threadIdx.x;
    const int l   = tid & 31;
    const int w   = tid >> 5;
    const int wm  = w >> 2;       // 0..3
    const int wn  = w & 3;        // 0..3

    const int bx = blockIdx.x;
    const int nt = bx & 3;
    const int mt = (bx >> 2) & 3;
    const int sp = bx >> 4;       // 0..8

    const int c0  = sp * CPS;
    int nch = NCHUNK - c0;
    if (nch > CPS) nch = CPS;

    // --- A staging geometry: thread covers rows [w*16, w*16+16), k = l ---
    const int am0 = mt * MT + w * 16;
    // --- B staging geometry: thread covers n = tid&127, k = (tid>>7)*8 + j ---
    const int bn  = tid & 127;
    const int bkg = tid >> 7;                 // 0..3
    const float* W1p = W1 + (size_t)(nt * NT + bn);

    // ---- A chunk load (16 floats) ----
    auto loadA = [&](int chunk, float aF[16]) {
        const int k = chunk * CHUNK + l;
        const float* src = 0; int stride = 0;
        if (k < B_AT)        { src = st  + k;           stride = ST_LEN;  }
        else if (k < B_ST1)  { src = at  + (k - B_AT);  stride = AT_LEN_; }
        else if (k < KTOT)   { src = st1 + (k - B_ST1); stride = ST1_LEN; }
        if (src) {
            const float* p = src + (size_t)am0 * stride;
#pragma unroll
            for (int r = 0; r < 16; ++r) { aF[r] = __ldg(p); p += stride; }
        } else {
#pragma unroll
            for (int r = 0; r < 16; ++r) aF[r] = 0.0f;
        }
    };
    auto storeA = [&](int s, const float aF[16]) {
        const uint32_t Ab = base + (uint32_t)s * STAGE;
#pragma unroll
        for (int r = 0; r < 16; ++r)
            sts32(Ab + swz((uint32_t)((w * 16 + r) * 128 + l * 4)), f32_to_tf32(aF[r]));
    };

    // ---- B chunk load (8 floats, transpose W1[k][n] -> smem[n][k]) ----
    auto loadB = [&](int chunk, float bF[8]) {
        const int kb = chunk * CHUNK + bkg * 8;
#pragma unroll
        for (int j = 0; j < 8; ++j) {
            const int k = kb + j;
            bF[j] = (k < KTOT) ? __ldg(W1p + (size_t)k * HID) : 0.0f;
        }
    };
    auto storeB = [&](int s, const float bF[8]) {
        const uint32_t Bb = base + (uint32_t)s * STAGE + A_BYTES;
        uint32_t t0 = f32_to_tf32(bF[0]), t1 = f32_to_tf32(bF[1]);
        uint32_t t2 = f32_to_tf32(bF[2]), t3 = f32_to_tf32(bF[3]);
        sts128(Bb + swz((uint32_t)(bn * 128 + (bkg * 8) * 4)), t0, t1, t2, t3);
        t0 = f32_to_tf32(bF[4]); t1 = f32_to_tf32(bF[5]);
        t2 = f32_to_tf32(bF[6]); t3 = f32_to_tf32(bF[7]);
        sts128(Bb + swz((uint32_t)(bn * 128 + (bkg * 8 + 4) * 4)), t0, t1, t2, t3);
    };

    // ---- fragment smem offsets (pre-swizzle, in-tile) ----
    uint32_t relA[4], relB[4];
#pragma unroll
    for (int t = 0; t < 4; ++t)
        relA[t] = (uint32_t)((wm * 64 + t * 16 + (l & 7) + ((l >> 3) & 1) * 8) * 128
                             + ((l >> 4) & 1) * 16);
    const int lm = l & 15;
#pragma unroll
    for (int u = 0; u < 4; ++u)
        relB[u] = (uint32_t)((wn * 32 + u * 8 + (lm & 7)) * 128 + ((lm >> 3) & 1) * 16);

    float acc[4][4][4];
#pragma unroll
    for (int t = 0; t < 4; ++t)
#pragma unroll
        for (int u = 0; u < 4; ++u)
#pragma unroll
            for (int j = 0; j < 4; ++j) acc[t][u][j] = 0.0f;

    // ---- prologue ----
    {
        float aF[16]; float bF[8];
        loadA(c0, aF); loadB(c0, bF);
        storeA(0, aF); storeB(0, bF);
    }
    __syncthreads();

    // ---- main loop ----
    for (int i = 0; i < nch; ++i) {
        const int s = i & 1;
        const uint32_t Ab = base + (uint32_t)s * STAGE;
        const uint32_t Bb = Ab + A_BYTES;
        const bool pf = (i + 1 < nch);

        float aF[16];
        if (pf) loadA(c0 + i + 1, aF);

        // compute ks = 0,1 (A load latency hidden here)
#pragma unroll
        for (int ks = 0; ks < 2; ++ks) {
            uint32_t afr[4][4], bfr[4][2];
#pragma unroll
            for (int t = 0; t < 4; ++t) ldsm_x4(afr[t], Ab + swz(relA[t] + ks * 32));
#pragma unroll
            for (int u = 0; u < 4; ++u) ldsm_x2(bfr[u], Bb + swz(relB[u] + ks * 32));
#pragma unroll
            for (int t = 0; t < 4; ++t)
#pragma unroll
                for (int u = 0; u < 4; ++u)
                    mma_tf32(acc[t][u], afr[t], bfr[u]);
        }

        float bF[8];
        if (pf) { storeA(s ^ 1, aF); loadB(c0 + i + 1, bF); }

        // compute ks = 2,3 (B load latency hidden here)
#pragma unroll
        for (int ks = 2; ks < 4; ++ks) {
            uint32_t afr[4][4], bfr[4][2];
#pragma unroll
            for (int t = 0; t < 4; ++t) ldsm_x4(afr[t], Ab + swz(relA[t] + ks * 32));
#pragma unroll
            for (int u = 0; u < 4; ++u) ldsm_x2(bfr[u], Bb + swz(relB[u] + ks * 32));
#pragma unroll
            for (int t = 0; t < 4; ++t)
#pragma unroll
                for (int u = 0; u < 4; ++u)
                    mma_tf32(acc[t][u], afr[t], bfr[u]);
        }

        if (pf) storeB(s ^ 1, bF);
        __syncthreads();
    }

    // ---- epilogue: write split-K partials ----
    float* outp = g_partial + (size_t)sp * BS_ * HID;
#pragma unroll
    for (int t = 0; t < 4; ++t) {
        const int row0 = mt * MT + wm * 64 + t * 16 + (l >> 2);
#pragma unroll
        for (int u = 0; u < 4; ++u) {
            const int col = nt * NT + wn * 32 + u * 8 + (l & 3) * 2;
            float2 v0; v0.x = acc[t][u][0]; v0.y = acc[t][u][1];
            float2 v1; v1.x = acc[t][u][2]; v1.y = acc[t][u][3];
            *(float2*)(outp + (size_t)row0 * HID + col)       = v0;
            *(float2*)(outp + (size_t)(row0 + 8) * HID + col) = v1;
        }
    }
}

// ----------------------------------------------------------------------------
// Kernel 2: reduce split-K partials + b1 + ReLU, then H @ W2 + b2.
// grid = 128 CTAs x 512 threads; 8 batch rows per CTA.
// ----------------------------------------------------------------------------
__global__ void __launch_bounds__(512) mlp2_kernel(
    const float* __restrict__ b1, const float* __restrict__ W2,
    const float* __restrict__ b2, float* __restrict__ out)
{
    __shared__ float h_s[8 * HID];   // 16 KB
    const int tid = threadIdx.x;
    const int row0 = blockIdx.x * 8;

    // Phase 1: vectorized 9-way reduce + b1 + ReLU. 8*128 float4 / 512 thr = 2 each.
#pragma unroll
    for (int q = tid; q < 8 * (HID / 4); q += 512) {
        const int r  = q >> 7;          // 0..7
        const int c4 = q & 127;         // float4 column
        float4 s = __ldg((const float4*)b1 + c4);
#pragma unroll
        for (int sp = 0; sp < SPLIT; ++sp) {
            float4 p = *((const float4*)g_partial +
                         ((size_t)sp * BS_ + (row0 + r)) * (HID / 4) + c4);
            s.x += p.x; s.y += p.y; s.z += p.z; s.w += p.w;
        }
        float4* dst = (float4*)h_s + r * (HID / 4) + c4;
        dst->x = fmaxf(s.x, 0.0f); dst->y = fmaxf(s.y, 0.0f);
        dst->z = fmaxf(s.z, 0.0f); dst->w = fmaxf(s.w, 0.0f);
    }
    __syncthreads();

    // Phase 2: 8*129 = 1032 dot products over 512 threads.
    for (int d = tid; d < 8 * ODIM; d += 512) {
        const int r = d / ODIM;
        const int j = d - r * ODIM;
        float acc = __ldg(b2 + j);
        const float* hrow = h_s + r * HID;
#pragma unroll 8
        for (int k = 0; k < HID; ++k)
            acc = fmaf(hrow[k], __ldg(W2 + k * ODIM + j), acc);
        out[(size_t)row0 * ODIM + d] = acc;
    }
}

// ----------------------------------------------------------------------------
// Launch
// ----------------------------------------------------------------------------
extern "C" void kernel_launch(void* const* d_in, const int* in_sizes, int n_in,
                              void* d_out, int out_size) {
    const float* st  = (const float*)d_in[0];
    const float* at  = (const float*)d_in[1];
    const float* st1 = (const float*)d_in[2];
    const float* W1  = (const float*)d_in[3];
    const float* b1  = (const float*)d_in[4];
    const float* W2  = (const float*)d_in[5];
    const float* b2  = (const float*)d_in[6];
    float* out = (float*)d_out;

    cudaFuncSetAttribute(gemm1_kernel, cudaFuncAttributeMaxDynamicSharedMemorySize, SMEM_TOTAL);

    gemm1_kernel<<<144, 512, SMEM_TOTAL>>>(st, at, st1, W1);
    mlp2_kernel<<<BS_ / 8, 512>>>(b1, W2, b2, out);
}